// round 8
// baseline (speedup 1.0000x reference)
#include <cuda_runtime.h>
#include <cstdint>

// Problem shape (fixed by dataset): N=50000 nodes, E=800000, K=8, D=64.
#define DDIM 64
#define MAX_NODES 50000
#define MAX_RELS 8
#define MAX_EDGES 800000
#define SCAN_CHUNK 1024
#define MAX_CHUNKS ((MAX_NODES + SCAN_CHUNK - 1) / SCAN_CHUNK)

// Scratch: hw[n][k][o] (102.4 MB), tf32 W9, CSR arrays, packed edge records.
__device__ float g_hw[(size_t)MAX_NODES * MAX_RELS * DDIM];
__device__ float g_w9[9 * DDIM * DDIM];
__device__ int g_deg[MAX_NODES];
__device__ int g_rowptr[MAX_NODES + 1];
__device__ int g_cursor[MAX_NODES];
__device__ int g_blocksum[MAX_CHUNKS];
__device__ int2 g_epack[MAX_EDGES];   // {src*8+rel, bits(norm)} in CSR order

__device__ __forceinline__ uint32_t rna_tf32(float v) {
    uint32_t u;
    asm("cvt.rna.tf32.f32 %0, %1;" : "=r"(u) : "f"(v));
    return u;
}

// m16n8k8 tf32 mma, fp32 accumulate.
__device__ __forceinline__ void mma_tf32(float* c,
    uint32_t a0, uint32_t a1, uint32_t a2, uint32_t a3,
    uint32_t b0, uint32_t b1)
{
    asm volatile(
        "mma.sync.aligned.m16n8k8.row.col.f32.tf32.tf32.f32 "
        "{%0,%1,%2,%3}, {%4,%5,%6,%7}, {%8,%9}, {%0,%1,%2,%3};"
        : "+f"(c[0]), "+f"(c[1]), "+f"(c[2]), "+f"(c[3])
        : "r"(a0), "r"(a1), "r"(a2), "r"(a3), "r"(b0), "r"(b1));
}

// ---------------------------------------------------------------------------
// prep: W ++ loop_weight -> tf32-rna in g_w9; zero g_deg and g_blocksum.
// ---------------------------------------------------------------------------
__global__ void prep_kernel(const float* __restrict__ W,
                            const float* __restrict__ lw,
                            int n_nodes, int nchunks)
{
    int i = blockIdx.x * blockDim.x + threadIdx.x;
    if (i < 9 * DDIM * DDIM) {
        float v = (i < MAX_RELS * DDIM * DDIM) ? W[i] : lw[i - MAX_RELS * DDIM * DDIM];
        g_w9[i] = __uint_as_float(rna_tf32(v));
    }
    if (i < n_nodes) g_deg[i] = 0;
    if (i < nchunks) g_blocksum[i] = 0;
}

// hist: per-node degree atomics + per-chunk counts via smem histogram.
__global__ __launch_bounds__(256) void hist_kernel(const int* __restrict__ dst,
                                                   int n_edges, int nchunks)
{
    __shared__ int sm_chunk[MAX_CHUNKS];
    int t = threadIdx.x;
    if (t < nchunks) sm_chunk[t] = 0;
    __syncthreads();

    int e = blockIdx.x * 256 + t;
    if (e < n_edges) {
        int d = dst[e];
        atomicAdd(&g_deg[d], 1);
        atomicAdd(&sm_chunk[d >> 10], 1);
    }
    __syncthreads();
    if (t < nchunks) {
        int c = sm_chunk[t];
        if (c) atomicAdd(&g_blocksum[t], c);
    }
}

// chunk_scan: shfl-based block scan of degrees + self-computed chunk offset.
// rowptr (exclusive) and cursor in one pass. scan_sums kernel folded in.
__global__ __launch_bounds__(SCAN_CHUNK) void chunk_scan_kernel(int n_nodes)
{
    __shared__ int warp_sums[32];
    __shared__ int warp_off[32];
    __shared__ int chunk_off_s;

    int t = threadIdx.x;
    int wid = t >> 5, lane = t & 31;
    int i = blockIdx.x * SCAN_CHUNK + t;
    int v = (i < n_nodes) ? g_deg[i] : 0;

    // warp inclusive scan
    int s = v;
#pragma unroll
    for (int off = 1; off < 32; off <<= 1) {
        int u = __shfl_up_sync(0xFFFFFFFFu, s, off);
        if (lane >= off) s += u;
    }
    if (lane == 31) warp_sums[wid] = s;
    __syncthreads();

    if (wid == 0) {
        // chunk offset = sum of blocksum[0..bid)
        int acc = 0;
        for (int j = lane; j < blockIdx.x; j += 32) acc += g_blocksum[j];
#pragma unroll
        for (int off = 16; off > 0; off >>= 1)
            acc += __shfl_xor_sync(0xFFFFFFFFu, acc, off);
        if (lane == 0) chunk_off_s = acc;

        // exclusive scan of the 32 warp sums
        int ws = warp_sums[lane];
        int wss = ws;
#pragma unroll
        for (int off = 1; off < 32; off <<= 1) {
            int u = __shfl_up_sync(0xFFFFFFFFu, wss, off);
            if (lane >= off) wss += u;
        }
        warp_off[lane] = wss - ws;
    }
    __syncthreads();

    if (i < n_nodes) {
        int excl = chunk_off_s + warp_off[wid] + s - v;
        g_rowptr[i] = excl;
        g_cursor[i] = excl;
        if (i == n_nodes - 1) g_rowptr[n_nodes] = excl + v;
    }
}

// Scatter edges into CSR order as packed int2 records.
__global__ void scatter_build_kernel(const int* __restrict__ src,
                                     const int* __restrict__ dst,
                                     const int* __restrict__ rel,
                                     const float* __restrict__ norm,
                                     int n_edges)
{
    int e = blockIdx.x * blockDim.x + threadIdx.x;
    if (e >= n_edges) return;
    int pos = atomicAdd(&g_cursor[dst[e]], 1);
    g_epack[pos] = make_int2(src[e] * MAX_RELS + rel[e], __float_as_int(norm[e]));
}

// ---------------------------------------------------------------------------
// Fused tensor-core GEMM (unchanged from the 143us kernel). Static smem.
// ---------------------------------------------------------------------------
#define A2_STRIDE 36

__global__ __launch_bounds__(256) void rgcn_gemm9_kernel(
    const float* __restrict__ h, const float* __restrict__ bias,
    float* __restrict__ out, int n_nodes)
{
    __shared__ uint2 A2[64 * A2_STRIDE];
    __shared__ uint2 B2[64 * A2_STRIDE];

    const int tid = threadIdx.x;
    const int gr0 = blockIdx.x * 64;

    {
        int row = tid >> 2;
        int q = tid & 3;
        int gr = gr0 + row;
        uint2* Arow = A2 + row * A2_STRIDE;
        if (gr < n_nodes) {
            const float4* hp = (const float4*)(h + (size_t)gr * DDIM);
#pragma unroll
            for (int kk = 0; kk < 2; ++kk) {
                int ks = 2 * q + kk;
                float4 v0 = hp[2 * ks];
                float4 v1 = hp[2 * ks + 1];
                Arow[4 * ks + 0] = make_uint2(rna_tf32(v0.x), rna_tf32(v1.x));
                Arow[4 * ks + 1] = make_uint2(rna_tf32(v0.y), rna_tf32(v1.y));
                Arow[4 * ks + 2] = make_uint2(rna_tf32(v0.z), rna_tf32(v1.z));
                Arow[4 * ks + 3] = make_uint2(rna_tf32(v0.w), rna_tf32(v1.w));
            }
        } else {
#pragma unroll
            for (int kk = 0; kk < 2; ++kk) {
                int ks = 2 * q + kk;
                Arow[4 * ks + 0] = make_uint2(0u, 0u);
                Arow[4 * ks + 1] = make_uint2(0u, 0u);
                Arow[4 * ks + 2] = make_uint2(0u, 0u);
                Arow[4 * ks + 3] = make_uint2(0u, 0u);
            }
        }
    }

    const int wid = tid >> 5;
    const int lane = tid & 31;
    const int g = lane >> 2;
    const int t = lane & 3;
    const int m0 = (wid & 3) * 16;
    const int nbase = (wid >> 2) * 32;

    const uint2* ar0 = A2 + (m0 + g) * A2_STRIDE + t;
    const uint2* ar1 = A2 + (m0 + g + 8) * A2_STRIDE + t;
    const uint2* brb = B2 + (nbase + g) * A2_STRIDE + t;

    const int row_lo = gr0 + m0 + g;
    const int row_hi = row_lo + 8;

    for (int rel = 0; rel < 9; ++rel) {
        __syncthreads();
        {
            const float* Wk = g_w9 + rel * DDIM * DDIM;
#pragma unroll
            for (int i = 0; i < 8; ++i) {
                int e = tid + i * 256;
                int n = e & 63;
                int p = e >> 6;
                int ks = p >> 2, tt = p & 3;
                uint32_t b0 = __float_as_uint(Wk[(8 * ks + tt) * DDIM + n]);
                uint32_t b1 = __float_as_uint(Wk[(8 * ks + tt + 4) * DDIM + n]);
                B2[n * A2_STRIDE + p] = make_uint2(b0, b1);
            }
        }
        __syncthreads();

        float acc[4][4];
#pragma unroll
        for (int j = 0; j < 4; ++j)
#pragma unroll
            for (int qq = 0; qq < 4; ++qq) acc[j][qq] = 0.f;

#pragma unroll
        for (int ks = 0; ks < 8; ++ks) {
            uint2 A0 = ar0[4 * ks];
            uint2 A1 = ar1[4 * ks];
#pragma unroll
            for (int j = 0; j < 4; ++j) {
                uint2 B = brb[j * 8 * A2_STRIDE + 4 * ks];
                mma_tf32(acc[j], A0.x, A1.x, A0.y, A1.y, B.x, B.y);
            }
        }

        if (rel < 8) {
#pragma unroll
            for (int j = 0; j < 4; ++j) {
                int col = nbase + 8 * j + 2 * t;
                if (row_lo < n_nodes)
                    *(float2*)&g_hw[((size_t)row_lo * MAX_RELS + rel) * DDIM + col] =
                        make_float2(acc[j][0], acc[j][1]);
                if (row_hi < n_nodes)
                    *(float2*)&g_hw[((size_t)row_hi * MAX_RELS + rel) * DDIM + col] =
                        make_float2(acc[j][2], acc[j][3]);
            }
        } else {
#pragma unroll
            for (int j = 0; j < 4; ++j) {
                int col = nbase + 8 * j + 2 * t;
                float b0 = bias[col], b1 = bias[col + 1];
                if (row_lo < n_nodes)
                    *(float2*)&out[(size_t)row_lo * DDIM + col] =
                        make_float2(acc[j][0] + b0, acc[j][1] + b1);
                if (row_hi < n_nodes)
                    *(float2*)&out[(size_t)row_hi * DDIM + col] =
                        make_float2(acc[j][2] + b0, acc[j][3] + b1);
            }
        }
    }
}

// ---------------------------------------------------------------------------
// Aggregation: TWO warps per dst node (each owns a 128B half-row; lane = one
// float). Halves the degree-tail pace-setter vs one warp/node. Packed 8B
// edge records, 4-way unrolled gathers, fused loop-term + ReLU.
// ---------------------------------------------------------------------------
__global__ __launch_bounds__(256) void agg_kernel(float* __restrict__ out, int n_nodes)
{
    int gwarp = (blockIdx.x * 256 + threadIdx.x) >> 5;
    int lane = threadIdx.x & 31;
    int node = gwarp >> 1;
    int col = ((gwarp & 1) << 5) + lane;   // 0..63
    if (node >= n_nodes) return;

    int beg = g_rowptr[node];
    int end = g_rowptr[node + 1];

    float acc = 0.f;
    int i = beg;
    for (; i + 3 < end; i += 4) {
        int2 p0 = g_epack[i + 0];
        int2 p1 = g_epack[i + 1];
        int2 p2 = g_epack[i + 2];
        int2 p3 = g_epack[i + 3];
        float v0 = g_hw[(size_t)p0.x * DDIM + col];
        float v1 = g_hw[(size_t)p1.x * DDIM + col];
        float v2 = g_hw[(size_t)p2.x * DDIM + col];
        float v3 = g_hw[(size_t)p3.x * DDIM + col];
        acc += v0 * __int_as_float(p0.y);
        acc += v1 * __int_as_float(p1.y);
        acc += v2 * __int_as_float(p2.y);
        acc += v3 * __int_as_float(p3.y);
    }
    for (; i < end; ++i) {
        int2 p = g_epack[i];
        acc += g_hw[(size_t)p.x * DDIM + col] * __int_as_float(p.y);
    }

    float* o = out + (size_t)node * DDIM + col;
    *o = fmaxf(*o + acc, 0.0f);
}

// ---------------------------------------------------------------------------
// Inputs (metadata order): h, norm, W, loop_weight, h_bias, src, dst, r
// ---------------------------------------------------------------------------
extern "C" void kernel_launch(void* const* d_in, const int* in_sizes, int n_in,
                              void* d_out, int out_size)
{
    const float* h    = (const float*)d_in[0];
    const float* norm = (const float*)d_in[1];
    const float* W    = (const float*)d_in[2];
    const float* lw   = (const float*)d_in[3];
    const float* bias = (const float*)d_in[4];
    const int*   src  = (const int*)d_in[5];
    const int*   dst  = (const int*)d_in[6];
    const int*   rel  = (const int*)d_in[7];
    float* out = (float*)d_out;

    int n_nodes = in_sizes[0] / DDIM;
    int n_edges = in_sizes[5];

    int nb_edges = (n_edges + 255) / 256;
    int nchunks = (n_nodes + SCAN_CHUNK - 1) / SCAN_CHUNK;

    // prep weights + zero counters
    int prep_n = (9 * DDIM * DDIM > n_nodes) ? 9 * DDIM * DDIM : n_nodes;
    prep_kernel<<<(prep_n + 255) / 256, 256>>>(W, lw, n_nodes, nchunks);

    // CSR build (4 kernels)
    hist_kernel<<<nb_edges, 256>>>(dst, n_edges, nchunks);
    chunk_scan_kernel<<<nchunks, SCAN_CHUNK>>>(n_nodes);
    scatter_build_kernel<<<nb_edges, 256>>>(src, dst, rel, norm, n_edges);

    // Fused tensor-core GEMM: g_hw (rels 0..7) + d_out = h@loop + bias
    int ntiles = (n_nodes + 63) / 64;
    rgcn_gemm9_kernel<<<ntiles, 256>>>(h, bias, out, n_nodes);

    // Per-node CSR aggregation + fused ReLU (2 warps/node, no fp atomics)
    long long agg_threads = (long long)n_nodes * 64;
    int nb_agg = (int)((agg_threads + 255) / 256);
    agg_kernel<<<nb_agg, 256>>>(out, n_nodes);
}